// round 10
// baseline (speedup 1.0000x reference)
#include <cuda_runtime.h>
#include <cuda_bf16.h>
#include <math.h>
#include <stdint.h>

#define NUM_J 23
#define NP 16
#define NT 256                 // vertices per CTA tile (8 warps x 4 n8-tiles x 8)
#define THREADS 256

#define OFF_W  0                              // float [256][23] = 23552 B
#define OFF_V  (NT*NUM_J*4)                   // 23552: float4 [256] = 4096 B
#define STAGE_BYTES (OFF_V + NT*16)           // 27648
#define POSE_STRIDE 772                       // floats per pose in epilogue (256*3+4)
#define EPI_BYTES (NP*POSE_STRIDE*4)          // 49408
#define SMEM_TOTAL EPI_BYTES                  // epilogue aliases staging

// M images, bf16 hi/lo, row-major [48 rows][48 u32-words] (2 bf16/word, K=96).
// Words 46,47 (j=23 pad) never written -> stay zero.
__device__ uint32_t g_Ahi[48 * 48];
__device__ uint32_t g_Alo[48 * 48];
// Pre-swizzled per-lane MMA A-fragments: [(kb*3+mt)*2+side][lane] -> 4 u32
__device__ uint4 g_Afrag[6 * 3 * 2 * 32];

// ---------------- helpers ----------------
__device__ __forceinline__ uint32_t pk2(float lo, float hi) {
    __nv_bfloat162 t = __floats2bfloat162_rn(lo, hi);
    return *reinterpret_cast<uint32_t*>(&t);
}
__device__ __forceinline__ uint32_t cvt2(float lo, float hi) {  // lo -> low half
    uint32_t r;
    asm("cvt.rn.bf16x2.f32 %0, %1, %2;" : "=r"(r) : "f"(hi), "f"(lo));
    return r;
}
__device__ __forceinline__ void split_bf(float v, float& h, float& l) {
    h = __bfloat162float(__float2bfloat16_rn(v));
    l = v - h;
}
__device__ __forceinline__ void mma16816(float (&d)[4],
                                         uint32_t a0, uint32_t a1, uint32_t a2, uint32_t a3,
                                         uint32_t b0, uint32_t b1) {
    asm volatile("mma.sync.aligned.m16n8k16.row.col.f32.bf16.bf16.f32 "
                 "{%0,%1,%2,%3}, {%4,%5,%6,%7}, {%8,%9}, {%0,%1,%2,%3};"
                 : "+f"(d[0]), "+f"(d[1]), "+f"(d[2]), "+f"(d[3])
                 : "r"(a0), "r"(a1), "r"(a2), "r"(a3), "r"(b0), "r"(b1));
}

// ---------------------------------------------------------------------------
// Kernel 1: setup. Rodrigues parallel; chain warp-per-pose (12 lanes/step);
// A emit (shift folded; valid since weight rows sum to 1); joints out; then
// pre-swizzle A into per-lane MMA fragment layout.
// ---------------------------------------------------------------------------
struct SetupArgs {
    const float* joints;
    const float* disp;
    const float* rnd;
    const float* prm[11];
    float* outJ;
};

__device__ const int   c_parents[NUM_J] = {-1,0,1,1,3,4,5,4,7,4,9,1,11,12,13,12,15,12,17,0,19,0,21};
__device__ const int   c_slot[NUM_J]    = { 0,-1,-1,1,2,3,-1,4,-1,5,-1,6,7,8,-1,9,-1,10,-1,-1,-1,-1,-1};
__device__ const float c_scale[11]      = {0.7853981633974483f, 1.5707963267948966f, 1.5707963267948966f,
                                           0.7853981633974483f, 0.7853981633974483f, 0.7853981633974483f,
                                           1.5707963267948966f, 1.5707963267948966f, 0.7853981633974483f,
                                           0.7853981633974483f, 0.7853981633974483f};

__global__ void lbs_setup(SetupArgs a) {
    __shared__ float sR[NP][NUM_J][12];
    __shared__ float sG[NP][NUM_J][12];
    __shared__ float sSh[NP][3];

    int t = threadIdx.x;
    int p = t / NUM_J;
    int j = t - p * NUM_J;

    if (t < NP) {
        sSh[t][0] = a.rnd[t*3+0] + 3.0f * tanhf(a.disp[t*3+0]);
        sSh[t][1] = a.rnd[t*3+1] + 3.0f * tanhf(a.disp[t*3+1]);
        sSh[t][2] = a.rnd[t*3+2] + 3.0f * tanhf(a.disp[t*3+2]);
    }
    if (t < NP * NUM_J) {
        float* R = sR[p][j];
        int s = c_slot[j];
        if (s < 0) {
            R[0]=1.f;R[1]=0.f;R[2]=0.f; R[3]=0.f;R[4]=1.f;R[5]=0.f; R[6]=0.f;R[7]=0.f;R[8]=1.f;
        } else {
            float sc = c_scale[s];
            float r0 = sc * tanhf(a.prm[s][p*3+0]);
            float r1 = sc * tanhf(a.prm[s][p*3+1]);
            float r2 = sc * tanhf(a.prm[s][p*3+2]);
            float ang = sqrtf(r0*r0 + r1*r1 + r2*r2 + 1e-16f);
            float inv = 1.0f / ang;
            float ax = r0*inv, ay = r1*inv, az = r2*inv;
            float sn = sinf(ang), cs = cosf(ang), omc = 1.0f - cs;
            R[0] = cs + omc*ax*ax;      R[1] = omc*ax*ay - sn*az;  R[2] = omc*ax*az + sn*ay;
            R[3] = omc*ax*ay + sn*az;   R[4] = cs + omc*ay*ay;     R[5] = omc*ay*az - sn*ax;
            R[6] = omc*ax*az - sn*ay;   R[7] = omc*ay*az + sn*ax;  R[8] = cs + omc*az*az;
        }
        int par = c_parents[j];
        float rel0 = a.joints[j*3+0], rel1 = a.joints[j*3+1], rel2 = a.joints[j*3+2];
        if (par >= 0) { rel0 -= a.joints[par*3+0]; rel1 -= a.joints[par*3+1]; rel2 -= a.joints[par*3+2]; }
        R[9] = rel0; R[10] = rel1; R[11] = rel2;
    }
    __syncthreads();

    // warp-per-pose chain
    {
        int wp = t >> 5, lane = t & 31;
        if (wp < NP) {
#pragma unroll 1
            for (int jj = 0; jj < NUM_J; jj++) {
                if (lane < 12) {
                    const float* Rj = sR[wp][jj];
                    float G;
                    if (jj == 0) {
                        G = Rj[lane];
                    } else {
                        const float* Gp = sG[wp][c_parents[jj]];
                        if (lane < 9) {
                            int r = lane / 3, c = lane - 3*(lane/3);
                            G = Gp[r*3+0]*Rj[c] + Gp[r*3+1]*Rj[3+c] + Gp[r*3+2]*Rj[6+c];
                        } else {
                            int r = lane - 9;
                            G = Gp[r*3+0]*Rj[9] + Gp[r*3+1]*Rj[10] + Gp[r*3+2]*Rj[11] + Gp[9+r];
                        }
                    }
                    sG[wp][jj][lane] = G;
                }
                __syncwarp();
            }
        }
    }
    __syncthreads();

    if (t < NP * NUM_J) {
        const float* G = sG[p][j];
        float sh0 = sSh[p][0], sh1 = sSh[p][1], sh2 = sSh[p][2];

        a.outJ[(p*NUM_J + j)*3 + 0] = G[9]  + sh0;
        a.outJ[(p*NUM_J + j)*3 + 1] = G[10] + sh1;
        a.outJ[(p*NUM_J + j)*3 + 2] = G[11] + sh2;

        float jr0 = a.joints[j*3+0], jr1 = a.joints[j*3+1], jr2 = a.joints[j*3+2];
        float tt[3];
        tt[0] = G[9]  - (G[0]*jr0 + G[1]*jr1 + G[2]*jr2) + sh0;
        tt[1] = G[10] - (G[3]*jr0 + G[4]*jr1 + G[5]*jr2) + sh1;
        tt[2] = G[11] - (G[6]*jr0 + G[7]*jr1 + G[8]*jr2) + sh2;

        for (int i = 0; i < 3; i++) {
            int m = 3*p + i;
            float vals[4] = {G[i*3+0], G[i*3+1], G[i*3+2], tt[i]};
            float h[4], l[4];
            for (int c = 0; c < 4; c++) split_bf(vals[c], h[c], l[c]);
            g_Ahi[m*48 + 2*j + 0] = pk2(h[0], h[1]);
            g_Ahi[m*48 + 2*j + 1] = pk2(h[2], h[3]);
            g_Alo[m*48 + 2*j + 0] = pk2(l[0], l[1]);
            g_Alo[m*48 + 2*j + 1] = pk2(l[2], l[3]);
        }
    }
    __syncthreads();   // g_Ahi/g_Alo visible block-wide

    // pre-swizzle into mma fragment layout:
    // a0 = [row][w0], a1 = [row+8][w0], a2 = [row][w0+4], a3 = [row+8][w0+4]
    // row = mt*16 + (lane>>2), w0 = kb*8 + (lane&3)
    for (int idx = t; idx < 6*3*2*32; idx += blockDim.x) {
        int lane = idx & 31;
        int rest = idx >> 5;
        int side = rest & 1;
        int mtkb = rest >> 1;
        int mt = mtkb % 3;
        int kb = mtkb / 3;
        int row = mt*16 + (lane >> 2);
        int w0  = kb*8 + (lane & 3);
        const uint32_t* S = side ? g_Alo : g_Ahi;
        uint4 f;
        f.x = S[row*48 + w0];
        f.y = S[(row+8)*48 + w0];
        f.z = S[row*48 + w0 + 4];
        f.w = S[(row+8)*48 + w0 + 4];
        g_Afrag[((kb*3 + mt)*2 + side)*32 + lane] = f;
    }
}

// ---------------------------------------------------------------------------
// Kernel 2: 256-vertex tile GEMM via mma.sync (bf16 hi/lo, 3 passes).
// Warp w owns n8 tiles {4w..4w+3}. A fragments LDG.128'd from hot-L1 g_Afrag
// (no smem staging, no ldmatrix). B fragments built in registers.
// ---------------------------------------------------------------------------
__global__ __launch_bounds__(THREADS, 2) void lbs_mma(const float* __restrict__ verts,
                                                      const float* __restrict__ weights,
                                                      float* __restrict__ out, int V) {
    __shared__ __align__(16) char smem[SMEM_TOTAL];
    float* sWf = (float*)(smem + OFF_W);
    float* sVf = (float*)(smem + OFF_V);

    int tid  = threadIdx.x;
    int lane = tid & 31;
    int warp = tid >> 5;
    int m4   = lane & 3;
    int grp  = lane >> 2;
    int v0   = blockIdx.x * NT;
    int nv   = min(NT, V - v0);

    // ---- stage weights (zero-fill tail); nv*23 % 4 == 0 for nv in {256,32} ----
    {
        const float4* src = (const float4*)(weights + (size_t)v0 * NUM_J);
        int wn4 = (nv * NUM_J) >> 2;
        for (int i = tid; i < (NT*NUM_J)/4; i += THREADS) {
            float4 f = make_float4(0.f, 0.f, 0.f, 0.f);
            if (i < wn4) f = __ldg(src + i);
            *(float4*)(sWf + i*4) = f;
        }
    }
    // ---- stage verts as (x,y,z,1), zeros beyond nv ----
    if (tid < NT) {
        sVf[tid*4 + 3] = 1.0f;
        if (tid >= nv) { sVf[tid*4+0] = 0.f; sVf[tid*4+1] = 0.f; sVf[tid*4+2] = 0.f; }
    }
    {
        int nf4 = (nv * 3) >> 2;
        if (tid < nf4) {
            float4 f = __ldg((const float4*)(verts + (size_t)v0*3) + tid);
            int e = tid * 4;
            sVf[(e/3)*4 + (e%3)] = f.x;
            sVf[((e+1)/3)*4 + ((e+1)%3)] = f.y;
            sVf[((e+2)/3)*4 + ((e+2)%3)] = f.z;
            sVf[((e+3)/3)*4 + ((e+3)%3)] = f.w;
        }
    }
    __syncthreads();

    // per-tile preload: vertex components + weight row offsets
    float vc0[4], vc1[4];
    int woff[4];
#pragma unroll
    for (int t = 0; t < 4; t++) {
        int vB = (warp*4 + t)*8 + grp;
        float4 vq = *(const float4*)(sVf + vB*4);
        vc0[t] = (m4 & 1) ? vq.z : vq.x;
        vc1[t] = (m4 & 1) ? vq.w : vq.y;
        woff[t] = vB * NUM_J;
    }

    float d[4][3][4];
#pragma unroll
    for (int t = 0; t < 4; t++)
#pragma unroll
        for (int mt = 0; mt < 3; mt++)
#pragma unroll
            for (int q = 0; q < 4; q++) d[t][mt][q] = 0.f;

    int jbase = m4 >> 1;
    const uint4* frag = g_Afrag + lane;

#pragma unroll
    for (int kb = 0; kb < 6; kb++) {
        int jl = 4*kb + jbase;
        int jh = jl + 2;
        uint32_t bh[4][2], bl[4][2];
#pragma unroll
        for (int t = 0; t < 4; t++) {
            float wl = sWf[woff[t] + jl];
            float wh = (jh < NUM_J) ? sWf[woff[t] + jh] : 0.f;
            float p0 = wl*vc0[t], p1 = wl*vc1[t], p2 = wh*vc0[t], p3 = wh*vc1[t];
            bh[t][0] = cvt2(p0, p1);
            bh[t][1] = cvt2(p2, p3);
            float h0 = __uint_as_float(bh[t][0] << 16);
            float h1 = __uint_as_float(bh[t][0] & 0xffff0000u);
            float h2 = __uint_as_float(bh[t][1] << 16);
            float h3 = __uint_as_float(bh[t][1] & 0xffff0000u);
            bl[t][0] = cvt2(p0 - h0, p1 - h1);
            bl[t][1] = cvt2(p2 - h2, p3 - h3);
        }
#pragma unroll
        for (int mt = 0; mt < 3; mt++) {
            uint4 ah = __ldg(frag + ((kb*3 + mt)*2 + 0)*32);
            mma16816(d[0][mt], ah.x, ah.y, ah.z, ah.w, bh[0][0], bh[0][1]);
            mma16816(d[1][mt], ah.x, ah.y, ah.z, ah.w, bh[1][0], bh[1][1]);
            mma16816(d[2][mt], ah.x, ah.y, ah.z, ah.w, bh[2][0], bh[2][1]);
            mma16816(d[3][mt], ah.x, ah.y, ah.z, ah.w, bh[3][0], bh[3][1]);
            mma16816(d[0][mt], ah.x, ah.y, ah.z, ah.w, bl[0][0], bl[0][1]);
            mma16816(d[1][mt], ah.x, ah.y, ah.z, ah.w, bl[1][0], bl[1][1]);
            mma16816(d[2][mt], ah.x, ah.y, ah.z, ah.w, bl[2][0], bl[2][1]);
            mma16816(d[3][mt], ah.x, ah.y, ah.z, ah.w, bl[3][0], bl[3][1]);
            uint4 al = __ldg(frag + ((kb*3 + mt)*2 + 1)*32);
            mma16816(d[0][mt], al.x, al.y, al.z, al.w, bh[0][0], bh[0][1]);
            mma16816(d[1][mt], al.x, al.y, al.z, al.w, bh[1][0], bh[1][1]);
            mma16816(d[2][mt], al.x, al.y, al.z, al.w, bh[2][0], bh[2][1]);
            mma16816(d[3][mt], al.x, al.y, al.z, al.w, bh[3][0], bh[3][1]);
        }
    }
    __syncthreads();

    // ---- epilogue: D -> smem in output layout [pose][v*3+i] ----
    float* sE = (float*)smem;
#pragma unroll
    for (int t = 0; t < 4; t++) {
        int vb = (warp*4 + t)*8 + 2*m4;
#pragma unroll
        for (int mt = 0; mt < 3; mt++) {
            int r0 = mt*16 + grp;
            int r1 = r0 + 8;
            int pA = r0/3, iA = r0 - 3*pA;
            int pB = r1/3, iB = r1 - 3*pB;
            sE[pA*POSE_STRIDE + vb*3     + iA] = d[t][mt][0];
            sE[pA*POSE_STRIDE + (vb+1)*3 + iA] = d[t][mt][1];
            sE[pB*POSE_STRIDE + vb*3     + iB] = d[t][mt][2];
            sE[pB*POSE_STRIDE + (vb+1)*3 + iB] = d[t][mt][3];
        }
    }
    __syncthreads();

    // ---- coalesced float4 copy out ----
    size_t V3 = (size_t)V * 3;
    int nf4 = (nv * 3) >> 2;                   // valid float4 per pose (192 or 24)
    for (int q = tid; q < NP * 192; q += THREADS) {
        int p = q / 192, r = q - p*192;
        if (r < nf4) {
            float4 val = *(const float4*)(sE + p*POSE_STRIDE + r*4);
            *(float4*)(out + (size_t)p*V3 + (size_t)v0*3 + r*4) = val;
        }
    }
}

// ---------------------------------------------------------------------------
extern "C" void kernel_launch(void* const* d_in, const int* in_sizes, int n_in,
                              void* d_out, int out_size) {
    const float* vertices = (const float*)d_in[0];   // (1,V,3)
    const float* joints   = (const float*)d_in[1];   // (1,23,3)
    const float* weights  = (const float*)d_in[2];   // (V,23)
    const float* disp     = (const float*)d_in[3];   // (16,1,3)
    const float* rnd      = (const float*)d_in[4];   // (16,3)

    int V = in_sizes[0] / 3;
    float* out = (float*)d_out;

    SetupArgs sa;
    sa.joints = joints;
    sa.disp   = disp;
    sa.rnd    = rnd;
    for (int i = 0; i < 11; i++) sa.prm[i] = (const float*)d_in[5 + i];
    sa.outJ = out + (size_t)NP * V * 3;

    lbs_setup<<<1, 512>>>(sa);
    int blocks = (V + NT - 1) / NT;
    lbs_mma<<<blocks, THREADS>>>(vertices, weights, out, V);
}

// round 11
// speedup vs baseline: 1.1598x; 1.1598x over previous
#include <cuda_runtime.h>
#include <cuda_bf16.h>
#include <math.h>
#include <stdint.h>

#define NUM_J 23
#define NP 16
#define NT 192                 // vertices per CTA tile (8 warps x 3 n8-tiles x 8)
#define THREADS 256
#define W_STRIDE 24            // padded weights row (col 23 = 0)

#define OFF_W  0                              // float [192][24] = 18432 B
#define OFF_V  (NT*W_STRIDE*4)                // 18432: float4 [192] = 3072 B
#define POSE_STRIDE 580                       // floats per pose in epilogue (192*3+4)
#define SMEM_TOTAL (NP*POSE_STRIDE*4)         // 37120 B (epilogue aliases staging)

// M images, bf16 hi/lo, row-major [48 rows][48 u32-words] (2 bf16/word, K=96).
__device__ uint32_t g_Ahi[48 * 48];
__device__ uint32_t g_Alo[48 * 48];
// Pre-swizzled per-lane MMA A-fragments: [(kb*3+mt)*2+side][lane] -> 4 u32
__device__ uint4 g_Afrag[6 * 3 * 2 * 32];

// ---------------- helpers ----------------
__device__ __forceinline__ uint32_t pk2(float lo, float hi) {
    __nv_bfloat162 t = __floats2bfloat162_rn(lo, hi);
    return *reinterpret_cast<uint32_t*>(&t);
}
__device__ __forceinline__ void split_bf(float v, float& h, float& l) {
    h = __bfloat162float(__float2bfloat16_rn(v));
    l = v - h;
}
__device__ __forceinline__ uint32_t prmt_hi(float a, float b) {   // {hi16(a), hi16(b)} -> {lo,hi}
    uint32_t r;
    asm("prmt.b32 %0, %1, %2, 0x7632;" : "=r"(r)
        : "r"(__float_as_uint(a)), "r"(__float_as_uint(b)));
    return r;
}
__device__ __forceinline__ float trunc_hi(float a) {
    return __uint_as_float(__float_as_uint(a) & 0xffff0000u);
}
__device__ __forceinline__ void mma16816(float (&d)[4],
                                         uint32_t a0, uint32_t a1, uint32_t a2, uint32_t a3,
                                         uint32_t b0, uint32_t b1) {
    asm volatile("mma.sync.aligned.m16n8k16.row.col.f32.bf16.bf16.f32 "
                 "{%0,%1,%2,%3}, {%4,%5,%6,%7}, {%8,%9}, {%0,%1,%2,%3};"
                 : "+f"(d[0]), "+f"(d[1]), "+f"(d[2]), "+f"(d[3])
                 : "r"(a0), "r"(a1), "r"(a2), "r"(a3), "r"(b0), "r"(b1));
}

// ---------------------------------------------------------------------------
// Kernel 1: setup (1 block x 512). Rodrigues parallel; chain warp-per-pose;
// A emit (shift folded; valid since weight rows sum to 1); joints out;
// pre-swizzle A into per-lane MMA fragment layout.
// ---------------------------------------------------------------------------
struct SetupArgs {
    const float* joints;
    const float* disp;
    const float* rnd;
    const float* prm[11];
    float* outJ;
};

__device__ const int   c_parents[NUM_J] = {-1,0,1,1,3,4,5,4,7,4,9,1,11,12,13,12,15,12,17,0,19,0,21};
__device__ const int   c_slot[NUM_J]    = { 0,-1,-1,1,2,3,-1,4,-1,5,-1,6,7,8,-1,9,-1,10,-1,-1,-1,-1,-1};
__device__ const float c_scale[11]      = {0.7853981633974483f, 1.5707963267948966f, 1.5707963267948966f,
                                           0.7853981633974483f, 0.7853981633974483f, 0.7853981633974483f,
                                           1.5707963267948966f, 1.5707963267948966f, 0.7853981633974483f,
                                           0.7853981633974483f, 0.7853981633974483f};

__global__ void lbs_setup(SetupArgs a) {
    __shared__ float sR[NP][NUM_J][12];
    __shared__ float sG[NP][NUM_J][12];
    __shared__ float sSh[NP][3];

    int t = threadIdx.x;
    int p = t / NUM_J;
    int j = t - p * NUM_J;

    if (t < NP) {
        sSh[t][0] = a.rnd[t*3+0] + 3.0f * tanhf(a.disp[t*3+0]);
        sSh[t][1] = a.rnd[t*3+1] + 3.0f * tanhf(a.disp[t*3+1]);
        sSh[t][2] = a.rnd[t*3+2] + 3.0f * tanhf(a.disp[t*3+2]);
    }
    if (t < NP * NUM_J) {
        float* R = sR[p][j];
        int s = c_slot[j];
        if (s < 0) {
            R[0]=1.f;R[1]=0.f;R[2]=0.f; R[3]=0.f;R[4]=1.f;R[5]=0.f; R[6]=0.f;R[7]=0.f;R[8]=1.f;
        } else {
            float sc = c_scale[s];
            float r0 = sc * tanhf(a.prm[s][p*3+0]);
            float r1 = sc * tanhf(a.prm[s][p*3+1]);
            float r2 = sc * tanhf(a.prm[s][p*3+2]);
            float ang = sqrtf(r0*r0 + r1*r1 + r2*r2 + 1e-16f);
            float inv = 1.0f / ang;
            float ax = r0*inv, ay = r1*inv, az = r2*inv;
            float sn = sinf(ang), cs = cosf(ang), omc = 1.0f - cs;
            R[0] = cs + omc*ax*ax;      R[1] = omc*ax*ay - sn*az;  R[2] = omc*ax*az + sn*ay;
            R[3] = omc*ax*ay + sn*az;   R[4] = cs + omc*ay*ay;     R[5] = omc*ay*az - sn*ax;
            R[6] = omc*ax*az - sn*ay;   R[7] = omc*ay*az + sn*ax;  R[8] = cs + omc*az*az;
        }
        int par = c_parents[j];
        float rel0 = a.joints[j*3+0], rel1 = a.joints[j*3+1], rel2 = a.joints[j*3+2];
        if (par >= 0) { rel0 -= a.joints[par*3+0]; rel1 -= a.joints[par*3+1]; rel2 -= a.joints[par*3+2]; }
        R[9] = rel0; R[10] = rel1; R[11] = rel2;
    }
    __syncthreads();

    // warp-per-pose chain: lane m computes G element m each step
    {
        int wp = t >> 5, lane = t & 31;
        if (wp < NP) {
#pragma unroll 1
            for (int jj = 0; jj < NUM_J; jj++) {
                if (lane < 12) {
                    const float* Rj = sR[wp][jj];
                    float G;
                    if (jj == 0) {
                        G = Rj[lane];
                    } else {
                        const float* Gp = sG[wp][c_parents[jj]];
                        if (lane < 9) {
                            int r = lane / 3, c = lane - 3*(lane/3);
                            G = Gp[r*3+0]*Rj[c] + Gp[r*3+1]*Rj[3+c] + Gp[r*3+2]*Rj[6+c];
                        } else {
                            int r = lane - 9;
                            G = Gp[r*3+0]*Rj[9] + Gp[r*3+1]*Rj[10] + Gp[r*3+2]*Rj[11] + Gp[9+r];
                        }
                    }
                    sG[wp][jj][lane] = G;
                }
                __syncwarp();
            }
        }
    }
    __syncthreads();

    if (t < NP * NUM_J) {
        const float* G = sG[p][j];
        float sh0 = sSh[p][0], sh1 = sSh[p][1], sh2 = sSh[p][2];

        a.outJ[(p*NUM_J + j)*3 + 0] = G[9]  + sh0;
        a.outJ[(p*NUM_J + j)*3 + 1] = G[10] + sh1;
        a.outJ[(p*NUM_J + j)*3 + 2] = G[11] + sh2;

        float jr0 = a.joints[j*3+0], jr1 = a.joints[j*3+1], jr2 = a.joints[j*3+2];
        float tt[3];
        tt[0] = G[9]  - (G[0]*jr0 + G[1]*jr1 + G[2]*jr2) + sh0;
        tt[1] = G[10] - (G[3]*jr0 + G[4]*jr1 + G[5]*jr2) + sh1;
        tt[2] = G[11] - (G[6]*jr0 + G[7]*jr1 + G[8]*jr2) + sh2;

        for (int i = 0; i < 3; i++) {
            int m = 3*p + i;
            float vals[4] = {G[i*3+0], G[i*3+1], G[i*3+2], tt[i]};
            float h[4], l[4];
            for (int c = 0; c < 4; c++) split_bf(vals[c], h[c], l[c]);
            g_Ahi[m*48 + 2*j + 0] = pk2(h[0], h[1]);
            g_Ahi[m*48 + 2*j + 1] = pk2(h[2], h[3]);
            g_Alo[m*48 + 2*j + 0] = pk2(l[0], l[1]);
            g_Alo[m*48 + 2*j + 1] = pk2(l[2], l[3]);
        }
    }
    __syncthreads();

    // pre-swizzle into mma fragment layout:
    // a0=[row][w0], a1=[row+8][w0], a2=[row][w0+4], a3=[row+8][w0+4]
    // row = mt*16 + (lane>>2), w0 = kb*8 + (lane&3)
    for (int idx = t; idx < 6*3*2*32; idx += blockDim.x) {
        int lane = idx & 31;
        int rest = idx >> 5;
        int side = rest & 1;
        int mtkb = rest >> 1;
        int mt = mtkb % 3;
        int kb = mtkb / 3;
        int row = mt*16 + (lane >> 2);
        int w0  = kb*8 + (lane & 3);
        const uint32_t* S = side ? g_Alo : g_Ahi;
        uint4 f;
        f.x = S[row*48 + w0];
        f.y = S[(row+8)*48 + w0];
        f.z = S[row*48 + w0 + 4];
        f.w = S[(row+8)*48 + w0 + 4];
        g_Afrag[((kb*3 + mt)*2 + side)*32 + lane] = f;
    }
}

// ---------------------------------------------------------------------------
// Kernel 2: 192-vertex tile GEMM via mma.sync (bf16 hi/lo, 3 passes).
// A fragments via hot-L1 LDG.128 (g_Afrag); B fragments built with
// truncation-split (PRMT/LOP/FADD only — no cvt in the hot loop).
// ---------------------------------------------------------------------------
__global__ __launch_bounds__(THREADS, 3) void lbs_mma(const float* __restrict__ verts,
                                                      const float* __restrict__ weights,
                                                      float* __restrict__ out, int V) {
    __shared__ __align__(16) char smem[SMEM_TOTAL];
    float* sWf = (float*)(smem + OFF_W);
    float* sVf = (float*)(smem + OFF_V);

    int tid  = threadIdx.x;
    int lane = tid & 31;
    int warp = tid >> 5;
    int m4   = lane & 3;
    int grp  = lane >> 2;
    int v0   = blockIdx.x * NT;
    int nv   = min(NT, V - v0);

    // ---- stage weights into padded [NT][24] layout, col 23 = 0 ----
    {
        const float* src = weights + (size_t)v0 * NUM_J;
        for (int i = tid; i < nv * NUM_J; i += THREADS) {
            int v = i / NUM_J, j = i - v * NUM_J;
            sWf[v * W_STRIDE + j] = __ldg(src + i);
        }
        for (int v = tid; v < NT; v += THREADS) sWf[v * W_STRIDE + 23] = 0.f;
        if (nv < NT) {   // zero tail rows (garbage would feed unstored columns, but keep clean)
            for (int i = tid; i < (NT - nv) * NUM_J; i += THREADS) {
                int v = nv + i / NUM_J, j = i % NUM_J;
                sWf[v * W_STRIDE + j] = 0.f;
            }
        }
    }
    // ---- stage verts as (x,y,z,1), zeros beyond nv ----
    if (tid < NT) {
        sVf[tid*4 + 3] = 1.0f;
        if (tid >= nv) { sVf[tid*4+0] = 0.f; sVf[tid*4+1] = 0.f; sVf[tid*4+2] = 0.f; }
    }
    {
        int nf4 = (nv * 3) >> 2;     // exact for nv in {192, 32}
        if (tid < nf4) {
            float4 f = __ldg((const float4*)(verts + (size_t)v0*3) + tid);
            int e = tid * 4;
            sVf[(e/3)*4 + (e%3)] = f.x;
            sVf[((e+1)/3)*4 + ((e+1)%3)] = f.y;
            sVf[((e+2)/3)*4 + ((e+2)%3)] = f.z;
            sVf[((e+3)/3)*4 + ((e+3)%3)] = f.w;
        }
    }
    __syncthreads();

    // per-tile preload: vertex components + padded weight row offsets
    float vc0[3], vc1[3];
    int woff[3];
#pragma unroll
    for (int t = 0; t < 3; t++) {
        int vB = (warp*3 + t)*8 + grp;
        float4 vq = *(const float4*)(sVf + vB*4);
        vc0[t] = (m4 & 1) ? vq.z : vq.x;
        vc1[t] = (m4 & 1) ? vq.w : vq.y;
        woff[t] = vB * W_STRIDE;
    }

    float d[3][3][4];
#pragma unroll
    for (int t = 0; t < 3; t++)
#pragma unroll
        for (int mt = 0; mt < 3; mt++)
#pragma unroll
            for (int q = 0; q < 4; q++) d[t][mt][q] = 0.f;

    int jbase = m4 >> 1;
    const uint4* frag = g_Afrag + lane;

#pragma unroll
    for (int kb = 0; kb < 6; kb++) {
        int jl = 4*kb + jbase;               // jh = jl+2 <= 23 (padded zero col)
        uint32_t bh[3][2], bl[3][2];
#pragma unroll
        for (int t = 0; t < 3; t++) {
            float wl = sWf[woff[t] + jl];
            float wh = sWf[woff[t] + jl + 2];
            float p0 = wl*vc0[t], p1 = wl*vc1[t], p2 = wh*vc0[t], p3 = wh*vc1[t];
            bh[t][0] = prmt_hi(p0, p1);
            bh[t][1] = prmt_hi(p2, p3);
            float l0 = p0 - trunc_hi(p0);
            float l1 = p1 - trunc_hi(p1);
            float l2 = p2 - trunc_hi(p2);
            float l3 = p3 - trunc_hi(p3);
            bl[t][0] = prmt_hi(l0, l1);
            bl[t][1] = prmt_hi(l2, l3);
        }
#pragma unroll
        for (int mt = 0; mt < 3; mt++) {
            uint4 ah = __ldg(frag + ((kb*3 + mt)*2 + 0)*32);
            mma16816(d[0][mt], ah.x, ah.y, ah.z, ah.w, bh[0][0], bh[0][1]);
            mma16816(d[1][mt], ah.x, ah.y, ah.z, ah.w, bh[1][0], bh[1][1]);
            mma16816(d[2][mt], ah.x, ah.y, ah.z, ah.w, bh[2][0], bh[2][1]);
            mma16816(d[0][mt], ah.x, ah.y, ah.z, ah.w, bl[0][0], bl[0][1]);
            mma16816(d[1][mt], ah.x, ah.y, ah.z, ah.w, bl[1][0], bl[1][1]);
            mma16816(d[2][mt], ah.x, ah.y, ah.z, ah.w, bl[2][0], bl[2][1]);
            uint4 al = __ldg(frag + ((kb*3 + mt)*2 + 1)*32);
            mma16816(d[0][mt], al.x, al.y, al.z, al.w, bh[0][0], bh[0][1]);
            mma16816(d[1][mt], al.x, al.y, al.z, al.w, bh[1][0], bh[1][1]);
            mma16816(d[2][mt], al.x, al.y, al.z, al.w, bh[2][0], bh[2][1]);
        }
    }
    __syncthreads();

    // ---- epilogue: D -> smem in output layout [pose][v*3+i] ----
    float* sE = (float*)smem;
#pragma unroll
    for (int t = 0; t < 3; t++) {
        int vb = (warp*3 + t)*8 + 2*m4;
#pragma unroll
        for (int mt = 0; mt < 3; mt++) {
            int r0 = mt*16 + grp;
            int r1 = r0 + 8;
            int pA = r0/3, iA = r0 - 3*pA;
            int pB = r1/3, iB = r1 - 3*pB;
            sE[pA*POSE_STRIDE + vb*3     + iA] = d[t][mt][0];
            sE[pA*POSE_STRIDE + (vb+1)*3 + iA] = d[t][mt][1];
            sE[pB*POSE_STRIDE + vb*3     + iB] = d[t][mt][2];
            sE[pB*POSE_STRIDE + (vb+1)*3 + iB] = d[t][mt][3];
        }
    }
    __syncthreads();

    // ---- coalesced float4 copy out ----
    size_t V3 = (size_t)V * 3;
    int nf4 = (nv * 3) >> 2;                   // valid float4 per pose (144 or 24)
    for (int q = tid; q < NP * 144; q += THREADS) {
        int p = q / 144, r = q - p*144;
        if (r < nf4) {
            float4 val = *(const float4*)(sE + p*POSE_STRIDE + r*4);
            *(float4*)(out + (size_t)p*V3 + (size_t)v0*3 + r*4) = val;
        }
    }
}

// ---------------------------------------------------------------------------
extern "C" void kernel_launch(void* const* d_in, const int* in_sizes, int n_in,
                              void* d_out, int out_size) {
    const float* vertices = (const float*)d_in[0];   // (1,V,3)
    const float* joints   = (const float*)d_in[1];   // (1,23,3)
    const float* weights  = (const float*)d_in[2];   // (V,23)
    const float* disp     = (const float*)d_in[3];   // (16,1,3)
    const float* rnd      = (const float*)d_in[4];   // (16,3)

    int V = in_sizes[0] / 3;
    float* out = (float*)d_out;

    SetupArgs sa;
    sa.joints = joints;
    sa.disp   = disp;
    sa.rnd    = rnd;
    for (int i = 0; i < 11; i++) sa.prm[i] = (const float*)d_in[5 + i];
    sa.outJ = out + (size_t)NP * V * 3;

    lbs_setup<<<1, 512>>>(sa);
    int blocks = (V + NT - 1) / NT;
    lbs_mma<<<blocks, THREADS>>>(vertices, weights, out, V);
}